// round 12
// baseline (speedup 1.0000x reference)
#include <cuda_runtime.h>
#include <cuda_bf16.h>

#define BATCH   8
#define NNODES  1024
#define IN_DIM  256
#define OUT_DIM 256
#define HEADS   8
#define HDIM    32
#define ROWS    (BATCH * NNODES)   // 8192
#define RPB     4                  // rows per attn block
#define M_MAX   160                // max neighbors/row (mean ~52, sd ~7)
#define SC_STR  161                // odd stride -> conflict-free per-head broadcast reads

#define GEMM_BLOCKS    512         // 4 x 128
#define COMPACT_BLOCKS 512
#define ROWS_PER_CB    (ROWS / COMPACT_BLOCKS)   // 16

// Scratch (device globals: allocation-free)
__device__ float g_inputs[ROWS * OUT_DIM];   // [B,N,H,D] = X @ W (fp32)
__device__ float g_self [ROWS * HEADS];      // [B,N,H]
__device__ float g_neigh[ROWS * HEADS];      // [B,N,H]
__device__ int   g_nbr  [ROWS * M_MAX];      // CSR-ish neighbor lists
__device__ int   g_cnt  [ROWS];              // neighbor counts

// ---------------- packed f32x2 helpers ----------------
__device__ __forceinline__ unsigned long long pack2(float lo, float hi) {
    unsigned long long r;
    asm("mov.b64 %0, {%1, %2};" : "=l"(r) : "f"(lo), "f"(hi));
    return r;
}
__device__ __forceinline__ void unpack2(unsigned long long v, float& lo, float& hi) {
    asm("mov.b64 {%0, %1}, %2;" : "=f"(lo), "=f"(hi) : "l"(v));
}
__device__ __forceinline__ unsigned long long fma2(unsigned long long a,
                                                   unsigned long long b,
                                                   unsigned long long c) {
    unsigned long long d;
    asm("fma.rn.f32x2 %0, %1, %2, %3;" : "=l"(d) : "l"(a), "l"(b), "l"(c));
    return d;
}

// ---------------- Kernel 1 (heterogeneous): GEMM blocks + A-compaction blocks ----
// Blocks [0, 512): inputs = X @ W with fused score projections (unchanged math).
// Blocks [512, 1024): compact nonzeros of A rows into g_nbr/g_cnt. These run
// concurrently with the GEMM wave and soak up the DRAM bandwidth the
// FMA-bound GEMM leaves idle.
#define BM 64
#define BN 64
#define BK 32

__global__ __launch_bounds__(256)
void gemm_compact_kernel(const float* __restrict__ X, const float* __restrict__ W,
                         const float* __restrict__ A,
                         float* __restrict__ out,
                         float* __restrict__ self_t, float* __restrict__ neigh_t,
                         const float* __restrict__ fc1, const float* __restrict__ fc2,
                         int* __restrict__ nbr_g, int* __restrict__ cnt_g) {
    __shared__ __align__(16) float As[BK][BM + 4];
    __shared__ __align__(16) float Bs[BK][BN + 4];
    __shared__ int scnt;

    const int t = threadIdx.x;

    if (blockIdx.x >= GEMM_BLOCKS) {
        // ---------------- compaction path ----------------
        const int row_base = (blockIdx.x - GEMM_BLOCKS) * ROWS_PER_CB;
        for (int rr = 0; rr < ROWS_PER_CB; rr++) {
            const int row = row_base + rr;
            if (t == 0) scnt = 0;
            __syncthreads();
            const float4 v = ((const float4*)(A + (long)row * NNODES))[t];
            int idx[4]; int c = 0;
            const int b0 = 4 * t;
            if (v.x != 0.0f) idx[c++] = b0 + 0;
            if (v.y != 0.0f) idx[c++] = b0 + 1;
            if (v.z != 0.0f) idx[c++] = b0 + 2;
            if (v.w != 0.0f) idx[c++] = b0 + 3;
            if (c) {
                int p = atomicAdd(&scnt, c);
                for (int i = 0; i < c; i++) nbr_g[row * M_MAX + p + i] = idx[i];
            }
            __syncthreads();
            if (t == 0) cnt_g[row] = scnt;
        }
        return;
    }

    // ---------------- GEMM path (known-good) ----------------
    const int n0 = (blockIdx.x & 3) * BN;
    const int m0 = (blockIdx.x >> 2) * BM;
    const int tx = t & 15;
    const int ty = t >> 4;

    unsigned long long acc[4][2];
#pragma unroll
    for (int i = 0; i < 4; i++) { acc[i][0] = 0ull; acc[i][1] = 0ull; }

    for (int k0 = 0; k0 < IN_DIM; k0 += BK) {
#pragma unroll
        for (int s = t; s < 512; s += 256) {
            int r = s >> 3;
            int c = (s & 7) << 2;
            float4 v = *(const float4*)&X[(m0 + r) * IN_DIM + k0 + c];
            As[c + 0][r] = v.x; As[c + 1][r] = v.y;
            As[c + 2][r] = v.z; As[c + 3][r] = v.w;
        }
#pragma unroll
        for (int s = t; s < 512; s += 256) {
            int r = s >> 4;
            int c = (s & 15) << 2;
            *(float4*)&Bs[r][c] = *(const float4*)&W[(k0 + r) * OUT_DIM + n0 + c];
        }
        __syncthreads();

#pragma unroll
        for (int k = 0; k < BK; k++) {
            float4 a = *(const float4*)&As[k][ty * 4];
            float4 b = *(const float4*)&Bs[k][tx * 4];
            unsigned long long b01 = pack2(b.x, b.y);
            unsigned long long b23 = pack2(b.z, b.w);
            unsigned long long a2;
            a2 = pack2(a.x, a.x); acc[0][0] = fma2(a2, b01, acc[0][0]); acc[0][1] = fma2(a2, b23, acc[0][1]);
            a2 = pack2(a.y, a.y); acc[1][0] = fma2(a2, b01, acc[1][0]); acc[1][1] = fma2(a2, b23, acc[1][1]);
            a2 = pack2(a.z, a.z); acc[2][0] = fma2(a2, b01, acc[2][0]); acc[2][1] = fma2(a2, b23, acc[2][1]);
            a2 = pack2(a.w, a.w); acc[3][0] = fma2(a2, b01, acc[3][0]); acc[3][1] = fma2(a2, b23, acc[3][1]);
        }
        __syncthreads();
    }

    const int col = n0 + tx * 4;
    const int h   = col >> 5;
    const int dd  = col & 31;
    const float f1x = fc1[h * HDIM + dd],     f1y = fc1[h * HDIM + dd + 1];
    const float f1z = fc1[h * HDIM + dd + 2], f1w = fc1[h * HDIM + dd + 3];
    const float f2x = fc2[h * HDIM + dd],     f2y = fc2[h * HDIM + dd + 1];
    const float f2z = fc2[h * HDIM + dd + 2], f2w = fc2[h * HDIM + dd + 3];

#pragma unroll
    for (int i = 0; i < 4; i++) {
        const int row = m0 + ty * 4 + i;
        float4 o;
        unpack2(acc[i][0], o.x, o.y);
        unpack2(acc[i][1], o.z, o.w);
        *(float4*)&out[row * OUT_DIM + col] = o;

        float s1 = o.x * f1x + o.y * f1y + o.z * f1z + o.w * f1w;
        float s2 = o.x * f2x + o.y * f2y + o.z * f2z + o.w * f2w;
#pragma unroll
        for (int off = 1; off < 8; off <<= 1) {
            s1 += __shfl_xor_sync(0xffffffffu, s1, off);
            s2 += __shfl_xor_sync(0xffffffffu, s2, off);
        }
        if ((tx & 7) == 0) {
            self_t [row * HEADS + h] = s1;
            neigh_t[row * HEADS + h] = s2;
        }
    }
}

// ---------------- Kernel 2: sparse softmax + aggregation, 4 rows/block ----------------
// CSR comes from kernel 1 (L2-resident, ~1.7MB). exp(-1e9) underflows to 0 in
// fp32 so the dense-masked softmax equals softmax over A's nonzeros.
__global__ __launch_bounds__(256)
void attn_kernel(const float* __restrict__ inp,
                 const float* __restrict__ self_t, const float* __restrict__ neigh_t,
                 const int* __restrict__ nbr_g, const int* __restrict__ cnt_g,
                 float* __restrict__ out) {
    __shared__ float sc[RPB][HEADS][SC_STR];   // ~20.6 KB
    __shared__ int   nbr[RPB][M_MAX];          // 2.5 KB
    __shared__ float s_self[RPB][HEADS];
    __shared__ float s_inv[RPB][HEADS];
    __shared__ int   s_cnt[RPB];

    const int blk  = blockIdx.x;
    const int row0 = blk * RPB;
    const int b    = row0 >> 10;
    const int t    = threadIdx.x;

    if (t < RPB) s_cnt[t] = cnt_g[row0 + t];
    if (t < RPB * HEADS) s_self[t >> 3][t & 7] = self_t[(row0 + (t >> 3)) * HEADS + (t & 7)];

    // ---- Phase 1: pull CSR rows into smem (64 threads per row, coalesced) ----
    {
        const int r = t >> 6, c = t & 63;
        const int M = cnt_g[row0 + r];         // broadcast L1 hit
        const int* src = nbr_g + (row0 + r) * M_MAX;
        for (int j = c; j < M; j += 64) nbr[r][j] = src[j];
    }
    __syncthreads();

    // ---- Phase 2: softmax weights. 32 (row,head) pairs over 8 warps ----
    {
        const int w = t >> 5, lane = t & 31;
        const float* nb = neigh_t + (long)b * NNODES * HEADS;
#pragma unroll
        for (int p = 0; p < 4; p++) {
            const int pair = w * 4 + p;
            const int pr = pair >> 3, ph = pair & 7;
            const int M = s_cnt[pr];
            const float sw = s_self[pr][ph];
            float mx = -1e30f;
            for (int j = lane; j < M; j += 32) {
                float s = sw + nb[nbr[pr][j] * HEADS + ph];
                s = (s > 0.0f) ? s : 0.01f * s;
                sc[pr][ph][j] = s;
                mx = fmaxf(mx, s);
            }
#pragma unroll
            for (int o = 16; o > 0; o >>= 1) mx = fmaxf(mx, __shfl_xor_sync(0xffffffffu, mx, o));
            float sum = 0.0f;
            for (int j = lane; j < M; j += 32) {
                float e = __expf(sc[pr][ph][j] - mx);
                sc[pr][ph][j] = e;
                sum += e;
            }
#pragma unroll
            for (int o = 16; o > 0; o >>= 1) sum += __shfl_xor_sync(0xffffffffu, sum, o);
            if (lane == 0) s_inv[pr][ph] = 1.0f / sum;
        }
    }
    __syncthreads();

    // ---- Phase 3: gather-aggregate. warp w -> (row w>>1, half w&1) ----
    {
        const int w = t >> 5, lane = t & 31;
        const int r  = w >> 1;
        const int cq = (w & 1) * 32 + lane;     // float4 column 0..63
        const int h  = cq >> 3;
        const int M  = s_cnt[r];
        const float* scr = sc[r][h];
        const int* nbrr = nbr[r];
        const float4* inpb = (const float4*)inp + (long)b * NNODES * (OUT_DIM / 4);

        float4 a0 = make_float4(0.f, 0.f, 0.f, 0.f);
        float4 a1 = make_float4(0.f, 0.f, 0.f, 0.f);
        float4 a2 = make_float4(0.f, 0.f, 0.f, 0.f);
        float4 a3 = make_float4(0.f, 0.f, 0.f, 0.f);
        int j = 0;
        for (; j + 3 < M; j += 4) {
            const int i0 = nbrr[j],     i1 = nbrr[j + 1];
            const int i2 = nbrr[j + 2], i3 = nbrr[j + 3];
            const float w0 = scr[j],     w1 = scr[j + 1];
            const float w2 = scr[j + 2], w3 = scr[j + 3];
            const float4 v0 = inpb[i0 * 64 + cq];
            const float4 v1 = inpb[i1 * 64 + cq];
            const float4 v2 = inpb[i2 * 64 + cq];
            const float4 v3 = inpb[i3 * 64 + cq];
            a0.x += w0 * v0.x; a0.y += w0 * v0.y; a0.z += w0 * v0.z; a0.w += w0 * v0.w;
            a1.x += w1 * v1.x; a1.y += w1 * v1.y; a1.z += w1 * v1.z; a1.w += w1 * v1.w;
            a2.x += w2 * v2.x; a2.y += w2 * v2.y; a2.z += w2 * v2.z; a2.w += w2 * v2.w;
            a3.x += w3 * v3.x; a3.y += w3 * v3.y; a3.z += w3 * v3.z; a3.w += w3 * v3.w;
        }
        for (; j < M; j++) {
            const int i0 = nbrr[j];
            const float w0 = scr[j];
            const float4 v0 = inpb[i0 * 64 + cq];
            a0.x += w0 * v0.x; a0.y += w0 * v0.y; a0.z += w0 * v0.z; a0.w += w0 * v0.w;
        }
        const float inv = s_inv[r][h];
        float4 o;
        o.x = fmaxf(((a0.x + a1.x) + (a2.x + a3.x)) * inv, 0.0f);
        o.y = fmaxf(((a0.y + a1.y) + (a2.y + a3.y)) * inv, 0.0f);
        o.z = fmaxf(((a0.z + a1.z) + (a2.z + a3.z)) * inv, 0.0f);
        o.w = fmaxf(((a0.w + a1.w) + (a2.w + a3.w)) * inv, 0.0f);
        *(float4*)&out[(long)(row0 + r) * OUT_DIM + cq * 4] = o;
    }
}

// ---------------- launch ----------------
extern "C" void kernel_launch(void* const* d_in, const int* in_sizes, int n_in,
                              void* d_out, int out_size) {
    const float* A   = (const float*)d_in[0];
    const float* X   = (const float*)d_in[1];
    const float* W   = (const float*)d_in[2];
    const float* fc1 = (const float*)d_in[3];
    const float* fc2 = (const float*)d_in[4];
    float* out = (float*)d_out;

    float *inp, *self_t, *neigh_t;
    int *nbr_g, *cnt_g;
    cudaGetSymbolAddress((void**)&inp,     g_inputs);
    cudaGetSymbolAddress((void**)&self_t,  g_self);
    cudaGetSymbolAddress((void**)&neigh_t, g_neigh);
    cudaGetSymbolAddress((void**)&nbr_g,   g_nbr);
    cudaGetSymbolAddress((void**)&cnt_g,   g_cnt);

    gemm_compact_kernel<<<GEMM_BLOCKS + COMPACT_BLOCKS, 256>>>(
        X, W, A, inp, self_t, neigh_t, fc1, fc2, nbr_g, cnt_g);
    attn_kernel<<<ROWS / RPB, 256>>>(inp, self_t, neigh_t, nbr_g, cnt_g, out);
}

// round 13
// speedup vs baseline: 1.3893x; 1.3893x over previous
#include <cuda_runtime.h>
#include <cuda_bf16.h>

#define BATCH   8
#define NNODES  1024
#define IN_DIM  256
#define OUT_DIM 256
#define HEADS   8
#define HDIM    32
#define ROWS    (BATCH * NNODES)   // 8192
#define RPB     4                  // rows per attn block
#define M_MAX   160                // max neighbors/row (mean ~52, sd ~7)
#define SC_STR  161                // odd stride -> conflict-free per-head broadcast reads

// Scratch (device globals: allocation-free)
__device__ float g_inputs[ROWS * OUT_DIM];   // [B,N,H,D] = X @ W (fp32)
__device__ float g_self [ROWS * HEADS];      // [B,N,H]
__device__ float g_neigh[ROWS * HEADS];      // [B,N,H]

// ---------------- packed f32x2 helpers ----------------
__device__ __forceinline__ unsigned long long pack2(float lo, float hi) {
    unsigned long long r;
    asm("mov.b64 %0, {%1, %2};" : "=l"(r) : "f"(lo), "f"(hi));
    return r;
}
__device__ __forceinline__ void unpack2(unsigned long long v, float& lo, float& hi) {
    asm("mov.b64 {%0, %1}, %2;" : "=f"(lo), "=f"(hi) : "l"(v));
}
__device__ __forceinline__ unsigned long long fma2(unsigned long long a,
                                                   unsigned long long b,
                                                   unsigned long long c) {
    unsigned long long d;
    asm("fma.rn.f32x2 %0, %1, %2, %3;" : "=l"(d) : "l"(a), "l"(b), "l"(c));
    return d;
}

// ---------------- Kernel 1: inputs = X @ W, fused score projections ----------------
// A-tile stored PRE-DUPLICATED as (a,a) float2 pairs so the mainloop needs no
// register-duplication MOVs: every FFMA2 operand comes straight from LDS.128.
#define BM 64
#define BN 64
#define BK 32
#define ASTR 66   // float2 row stride: 66*8=528B, 16B-aligned rows

__global__ __launch_bounds__(256)
void gemm_kernel(const float* __restrict__ X, const float* __restrict__ W,
                 float* __restrict__ out,
                 float* __restrict__ self_t, float* __restrict__ neigh_t,
                 const float* __restrict__ fc1, const float* __restrict__ fc2) {
    __shared__ __align__(16) float2 As[BK][ASTR];   // dup pairs [k][m] (~16.9 KB)
    __shared__ __align__(16) float  Bs[BK][BN + 4]; // [k][n]

    const int t  = threadIdx.x;
    const int n0 = blockIdx.x * BN;
    const int m0 = blockIdx.y * BM;
    const int tx = t & 15;
    const int ty = t >> 4;

    unsigned long long acc[4][2];
#pragma unroll
    for (int i = 0; i < 4; i++) { acc[i][0] = 0ull; acc[i][1] = 0ull; }

    for (int k0 = 0; k0 < IN_DIM; k0 += BK) {
#pragma unroll
        for (int s = t; s < 512; s += 256) {
            int r = s >> 3;
            int c = (s & 7) << 2;
            float4 v = *(const float4*)&X[(m0 + r) * IN_DIM + k0 + c];
            As[c + 0][r] = make_float2(v.x, v.x);
            As[c + 1][r] = make_float2(v.y, v.y);
            As[c + 2][r] = make_float2(v.z, v.z);
            As[c + 3][r] = make_float2(v.w, v.w);
        }
#pragma unroll
        for (int s = t; s < 512; s += 256) {
            int r = s >> 4;
            int c = (s & 15) << 2;
            *(float4*)&Bs[r][c] = *(const float4*)&W[(k0 + r) * OUT_DIM + n0 + c];
        }
        __syncthreads();

#pragma unroll
        for (int k = 0; k < BK; k++) {
            const float4 a01 = *(const float4*)&As[k][ty * 4];      // (a0,a0,a1,a1)
            const float4 a23 = *(const float4*)&As[k][ty * 4 + 2];  // (a2,a2,a3,a3)
            const float4 b   = *(const float4*)&Bs[k][tx * 4];
            const unsigned long long b01 = pack2(b.x, b.y);   // adjacent regs: free
            const unsigned long long b23 = pack2(b.z, b.w);
            const unsigned long long a0p = pack2(a01.x, a01.y);
            const unsigned long long a1p = pack2(a01.z, a01.w);
            const unsigned long long a2p = pack2(a23.x, a23.y);
            const unsigned long long a3p = pack2(a23.z, a23.w);
            acc[0][0] = fma2(a0p, b01, acc[0][0]); acc[0][1] = fma2(a0p, b23, acc[0][1]);
            acc[1][0] = fma2(a1p, b01, acc[1][0]); acc[1][1] = fma2(a1p, b23, acc[1][1]);
            acc[2][0] = fma2(a2p, b01, acc[2][0]); acc[2][1] = fma2(a2p, b23, acc[2][1]);
            acc[3][0] = fma2(a3p, b01, acc[3][0]); acc[3][1] = fma2(a3p, b23, acc[3][1]);
        }
        __syncthreads();
    }

    // ---- epilogue: fp32 store + fused score projections (unchanged) ----
    const int col = n0 + tx * 4;
    const int h   = col >> 5;
    const int dd  = col & 31;
    const float f1x = fc1[h * HDIM + dd],     f1y = fc1[h * HDIM + dd + 1];
    const float f1z = fc1[h * HDIM + dd + 2], f1w = fc1[h * HDIM + dd + 3];
    const float f2x = fc2[h * HDIM + dd],     f2y = fc2[h * HDIM + dd + 1];
    const float f2z = fc2[h * HDIM + dd + 2], f2w = fc2[h * HDIM + dd + 3];

#pragma unroll
    for (int i = 0; i < 4; i++) {
        const int row = m0 + ty * 4 + i;
        float4 o;
        unpack2(acc[i][0], o.x, o.y);
        unpack2(acc[i][1], o.z, o.w);
        *(float4*)&out[row * OUT_DIM + col] = o;

        float s1 = o.x * f1x + o.y * f1y + o.z * f1z + o.w * f1w;
        float s2 = o.x * f2x + o.y * f2y + o.z * f2z + o.w * f2w;
#pragma unroll
        for (int off = 1; off < 8; off <<= 1) {
            s1 += __shfl_xor_sync(0xffffffffu, s1, off);
            s2 += __shfl_xor_sync(0xffffffffu, s2, off);
        }
        if ((tx & 7) == 0) {
            self_t [row * HEADS + h] = s1;
            neigh_t[row * HEADS + h] = s2;
        }
    }
}

// ---------------- Kernel 2: sparse softmax + aggregation, 4 rows/block ----------------
// (byte-identical to R10 — known-good 53.3 us)
__global__ __launch_bounds__(256)
void attn_kernel(const float* __restrict__ A,
                 const float* __restrict__ inp,
                 const float* __restrict__ self_t, const float* __restrict__ neigh_t,
                 float* __restrict__ out) {
    __shared__ float sc[RPB][HEADS][SC_STR];   // ~20.6 KB
    __shared__ int   nbr[RPB][M_MAX];          // 2.5 KB (raw indices)
    __shared__ float s_self[RPB][HEADS];
    __shared__ float s_inv[RPB][HEADS];
    __shared__ int   s_cnt[RPB];

    const int blk  = blockIdx.x;
    const int row0 = blk * RPB;
    const int b    = row0 >> 10;
    const int t    = threadIdx.x;

    if (t < RPB) s_cnt[t] = 0;
    if (t < RPB * HEADS) s_self[t >> 3][t & 7] = self_t[(row0 + (t >> 3)) * HEADS + (t & 7)];
    __syncthreads();

    // ---- Phase 1: compact nonzeros of 4 rows of A (64 threads/row, 4 loads MLP) ----
    {
        const int r   = t >> 6;
        const int c64 = t & 63;
        const float4* Arow = (const float4*)(A + (long)(row0 + r) * NNODES);
        const float4 v0 = Arow[c64];
        const float4 v1 = Arow[c64 + 64];
        const float4 v2 = Arow[c64 + 128];
        const float4 v3 = Arow[c64 + 192];
        int idx[8]; int c = 0;
        const int b0 = c64 * 4;
        if (v0.x != 0.0f) idx[c++] = b0 + 0;
        if (v0.y != 0.0f) idx[c++] = b0 + 1;
        if (v0.z != 0.0f) idx[c++] = b0 + 2;
        if (v0.w != 0.0f) idx[c++] = b0 + 3;
        if (v1.x != 0.0f) idx[c++] = b0 + 256;
        if (v1.y != 0.0f) idx[c++] = b0 + 257;
        if (v1.z != 0.0f) idx[c++] = b0 + 258;
        if (v1.w != 0.0f) idx[c++] = b0 + 259;
        int idx2[8]; int c2 = 0;
        if (v2.x != 0.0f) idx2[c2++] = b0 + 512;
        if (v2.y != 0.0f) idx2[c2++] = b0 + 513;
        if (v2.z != 0.0f) idx2[c2++] = b0 + 514;
        if (v2.w != 0.0f) idx2[c2++] = b0 + 515;
        if (v3.x != 0.0f) idx2[c2++] = b0 + 768;
        if (v3.y != 0.0f) idx2[c2++] = b0 + 769;
        if (v3.z != 0.0f) idx2[c2++] = b0 + 770;
        if (v3.w != 0.0f) idx2[c2++] = b0 + 771;
        if (c + c2) {
            int p = atomicAdd(&s_cnt[r], c + c2);
            for (int i = 0; i < c; i++)  nbr[r][p + i] = idx[i];
            for (int i = 0; i < c2; i++) nbr[r][p + c + i] = idx2[i];
        }
    }
    __syncthreads();

    // ---- Phase 2: softmax weights. 32 (row,head) pairs over 8 warps ----
    {
        const int w = t >> 5, lane = t & 31;
        const float* nb = neigh_t + (long)b * NNODES * HEADS;
#pragma unroll
        for (int p = 0; p < 4; p++) {
            const int pair = w * 4 + p;
            const int pr = pair >> 3, ph = pair & 7;
            const int M = s_cnt[pr];
            const float sw = s_self[pr][ph];
            float mx = -1e30f;
            for (int j = lane; j < M; j += 32) {
                float s = sw + nb[nbr[pr][j] * HEADS + ph];
                s = (s > 0.0f) ? s : 0.01f * s;
                sc[pr][ph][j] = s;
                mx = fmaxf(mx, s);
            }
#pragma unroll
            for (int o = 16; o > 0; o >>= 1) mx = fmaxf(mx, __shfl_xor_sync(0xffffffffu, mx, o));
            float sum = 0.0f;
            for (int j = lane; j < M; j += 32) {
                float e = __expf(sc[pr][ph][j] - mx);
                sc[pr][ph][j] = e;
                sum += e;
            }
#pragma unroll
            for (int o = 16; o > 0; o >>= 1) sum += __shfl_xor_sync(0xffffffffu, sum, o);
            if (lane == 0) s_inv[pr][ph] = 1.0f / sum;
        }
    }
    __syncthreads();

    // ---- Phase 3: gather-aggregate. warp w -> (row w>>1, half w&1) ----
    {
        const int w = t >> 5, lane = t & 31;
        const int r  = w >> 1;
        const int cq = (w & 1) * 32 + lane;      // float4 column 0..63
        const int h  = cq >> 3;
        const int M  = s_cnt[r];
        const float* scr = sc[r][h];
        const int* nbrr = nbr[r];
        const float4* inpb = (const float4*)inp + (long)b * NNODES * (OUT_DIM / 4);

        float4 a0 = make_float4(0.f, 0.f, 0.f, 0.f);
        float4 a1 = make_float4(0.f, 0.f, 0.f, 0.f);
        float4 a2 = make_float4(0.f, 0.f, 0.f, 0.f);
        float4 a3 = make_float4(0.f, 0.f, 0.f, 0.f);
        int j = 0;
        for (; j + 3 < M; j += 4) {
            const int i0 = nbrr[j],     i1 = nbrr[j + 1];
            const int i2 = nbrr[j + 2], i3 = nbrr[j + 3];
            const float w0 = scr[j],     w1 = scr[j + 1];
            const float w2 = scr[j + 2], w3 = scr[j + 3];
            const float4 v0 = inpb[i0 * 64 + cq];
            const float4 v1 = inpb[i1 * 64 + cq];
            const float4 v2 = inpb[i2 * 64 + cq];
            const float4 v3 = inpb[i3 * 64 + cq];
            a0.x += w0 * v0.x; a0.y += w0 * v0.y; a0.z += w0 * v0.z; a0.w += w0 * v0.w;
            a1.x += w1 * v1.x; a1.y += w1 * v1.y; a1.z += w1 * v1.z; a1.w += w1 * v1.w;
            a2.x += w2 * v2.x; a2.y += w2 * v2.y; a2.z += w2 * v2.z; a2.w += w2 * v2.w;
            a3.x += w3 * v3.x; a3.y += w3 * v3.y; a3.z += w3 * v3.z; a3.w += w3 * v3.w;
        }
        for (; j < M; j++) {
            const int i0 = nbrr[j];
            const float w0 = scr[j];
            const float4 v0 = inpb[i0 * 64 + cq];
            a0.x += w0 * v0.x; a0.y += w0 * v0.y; a0.z += w0 * v0.z; a0.w += w0 * v0.w;
        }
        const float inv = s_inv[r][h];
        float4 o;
        o.x = fmaxf(((a0.x + a1.x) + (a2.x + a3.x)) * inv, 0.0f);
        o.y = fmaxf(((a0.y + a1.y) + (a2.y + a3.y)) * inv, 0.0f);
        o.z = fmaxf(((a0.z + a1.z) + (a2.z + a3.z)) * inv, 0.0f);
        o.w = fmaxf(((a0.w + a1.w) + (a2.w + a3.w)) * inv, 0.0f);
        *(float4*)&out[(long)(row0 + r) * OUT_DIM + cq * 4] = o;
    }
}

// ---------------- launch ----------------
extern "C" void kernel_launch(void* const* d_in, const int* in_sizes, int n_in,
                              void* d_out, int out_size) {
    const float* A   = (const float*)d_in[0];
    const float* X   = (const float*)d_in[1];
    const float* W   = (const float*)d_in[2];
    const float* fc1 = (const float*)d_in[3];
    const float* fc2 = (const float*)d_in[4];
    float* out = (float*)d_out;

    float *inp, *self_t, *neigh_t;
    cudaGetSymbolAddress((void**)&inp,     g_inputs);
    cudaGetSymbolAddress((void**)&self_t,  g_self);
    cudaGetSymbolAddress((void**)&neigh_t, g_neigh);

    dim3 ggrid(OUT_DIM / BN, ROWS / BM);   // (4, 128)
    gemm_kernel<<<ggrid, 256>>>(X, W, inp, self_t, neigh_t, fc1, fc2);
    attn_kernel<<<ROWS / RPB, 256>>>(A, inp, self_t, neigh_t, out);
}

// round 14
// speedup vs baseline: 1.8956x; 1.3644x over previous
#include <cuda_runtime.h>
#include <cuda_bf16.h>

#define BATCH   8
#define NNODES  1024
#define IN_DIM  256
#define OUT_DIM 256
#define HEADS   8
#define HDIM    32
#define ROWS    (BATCH * NNODES)   // 8192
#define RPB     4
#define M_MAX   160
#define SC_STR  161

// Scratch (device globals: allocation-free)
__device__ float g_inputs[ROWS * OUT_DIM];   // [B,N,H,D] = X @ W (fp32 out, tf32 math)
__device__ float g_self [ROWS * HEADS];
__device__ float g_neigh[ROWS * HEADS];

__device__ __forceinline__ unsigned int f2tf32(float f) {
    unsigned int u;
    asm("cvt.rna.tf32.f32 %0, %1;" : "=r"(u) : "f"(f));
    return u;
}

// ---------------- Kernel 1: inputs = X @ W via tf32 mma.sync ----------------
// BM=128, BN=64, BK=32. 8 warps, warp tile 32x32 = 2x4 m16n8k8 tiles.
#define BM 128
#define BN 64
#define BK 32
#define AS_STR 36   // uint32 stride; lane addr (4*gid+tig)%32 -> conflict-free
#define BS_STR 72   // uint32 stride; lane addr (8*tig+gid)%32 -> conflict-free

__global__ __launch_bounds__(256)
void gemm_tf32_kernel(const float* __restrict__ X, const float* __restrict__ W,
                      float* __restrict__ out) {
    __shared__ __align__(16) unsigned int As[BM][AS_STR];  // tf32 [m][k] (18.4 KB)
    __shared__ __align__(16) unsigned int Bs[BK][BS_STR];  // tf32 [k][n] (9.2 KB)

    const int t    = threadIdx.x;
    const int warp = t >> 5;
    const int lane = t & 31;
    const int gid  = lane >> 2;     // group id 0..7
    const int tig  = lane & 3;      // thread-in-group 0..3
    const int wm   = warp & 3;      // warp m-tile 0..3
    const int wn   = warp >> 2;     // warp n-tile 0..1
    const int n0 = blockIdx.x * BN;
    const int m0 = blockIdx.y * BM;

    float acc[2][4][4];
#pragma unroll
    for (int mi = 0; mi < 2; mi++)
#pragma unroll
        for (int ni = 0; ni < 4; ni++)
#pragma unroll
            for (int q = 0; q < 4; q++) acc[mi][ni][q] = 0.0f;

    for (int k0 = 0; k0 < IN_DIM; k0 += BK) {
        // A tile: 128x32 -> 1024 float4 slots (4 per thread)
#pragma unroll
        for (int i = 0; i < 4; i++) {
            int s = t + i * 256;
            int r = s >> 3;
            int c = (s & 7) << 2;
            float4 v = *(const float4*)&X[(m0 + r) * IN_DIM + k0 + c];
            uint4 u;
            u.x = f2tf32(v.x); u.y = f2tf32(v.y);
            u.z = f2tf32(v.z); u.w = f2tf32(v.w);
            *(uint4*)&As[r][c] = u;
        }
        // B tile: 32x64 -> 512 float4 slots (2 per thread)
#pragma unroll
        for (int i = 0; i < 2; i++) {
            int s = t + i * 256;
            int r = s >> 4;
            int c = (s & 15) << 2;
            float4 v = *(const float4*)&W[(k0 + r) * OUT_DIM + n0 + c];
            uint4 u;
            u.x = f2tf32(v.x); u.y = f2tf32(v.y);
            u.z = f2tf32(v.z); u.w = f2tf32(v.w);
            *(uint4*)&Bs[r][c] = u;
        }
        __syncthreads();

#pragma unroll
        for (int k8 = 0; k8 < 4; k8++) {
            const int kc = k8 * 8 + tig;
            unsigned int a[2][4];
#pragma unroll
            for (int mi = 0; mi < 2; mi++) {
                const int r = wm * 32 + mi * 16 + gid;
                a[mi][0] = As[r][kc];
                a[mi][1] = As[r + 8][kc];
                a[mi][2] = As[r][kc + 4];
                a[mi][3] = As[r + 8][kc + 4];
            }
            unsigned int bfr[4][2];
#pragma unroll
            for (int ni = 0; ni < 4; ni++) {
                const int cb = wn * 32 + ni * 8 + gid;
                bfr[ni][0] = Bs[kc][cb];
                bfr[ni][1] = Bs[kc + 4][cb];
            }
#pragma unroll
            for (int mi = 0; mi < 2; mi++)
#pragma unroll
                for (int ni = 0; ni < 4; ni++) {
                    asm volatile(
                        "mma.sync.aligned.m16n8k8.row.col.f32.tf32.tf32.f32 "
                        "{%0,%1,%2,%3}, {%4,%5,%6,%7}, {%8,%9}, {%0,%1,%2,%3};\n"
                        : "+f"(acc[mi][ni][0]), "+f"(acc[mi][ni][1]),
                          "+f"(acc[mi][ni][2]), "+f"(acc[mi][ni][3])
                        : "r"(a[mi][0]), "r"(a[mi][1]), "r"(a[mi][2]), "r"(a[mi][3]),
                          "r"(bfr[ni][0]), "r"(bfr[ni][1]));
                }
        }
        __syncthreads();
    }

    // epilogue: c0/c1 -> (row, col..col+1), c2/c3 -> (row+8, same cols)
#pragma unroll
    for (int mi = 0; mi < 2; mi++) {
        const int row = m0 + wm * 32 + mi * 16 + gid;
#pragma unroll
        for (int ni = 0; ni < 4; ni++) {
            const int col = n0 + wn * 32 + ni * 8 + tig * 2;
            *(float2*)&out[row * OUT_DIM + col] =
                make_float2(acc[mi][ni][0], acc[mi][ni][1]);
            *(float2*)&out[(row + 8) * OUT_DIM + col] =
                make_float2(acc[mi][ni][2], acc[mi][ni][3]);
        }
    }
}

// ---------------- Kernel 2: score projections (R1 known-good, ~4us) ----------------
__global__ __launch_bounds__(256)
void scores_kernel(const float* __restrict__ inp,
                   const float* __restrict__ fc1, const float* __restrict__ fc2,
                   float* __restrict__ self_t, float* __restrict__ neigh_t) {
    const int bn = blockIdx.x;           // 0..8191
    const int t  = threadIdx.x;
    const int h  = t >> 5;
    const int d  = t & 31;
    float v  = inp[bn * OUT_DIM + t];
    float s1 = v * fc1[h * HDIM + d];
    float s2 = v * fc2[h * HDIM + d];
#pragma unroll
    for (int o = 16; o > 0; o >>= 1) {
        s1 += __shfl_xor_sync(0xffffffffu, s1, o);
        s2 += __shfl_xor_sync(0xffffffffu, s2, o);
    }
    if (d == 0) {
        self_t [bn * HEADS + h] = s1;
        neigh_t[bn * HEADS + h] = s2;
    }
}

// ---------------- Kernel 3: sparse softmax + aggregation (R10 exact) ----------------
__global__ __launch_bounds__(256)
void attn_kernel(const float* __restrict__ A,
                 const float* __restrict__ inp,
                 const float* __restrict__ self_t, const float* __restrict__ neigh_t,
                 float* __restrict__ out) {
    __shared__ float sc[RPB][HEADS][SC_STR];
    __shared__ int   nbr[RPB][M_MAX];
    __shared__ float s_self[RPB][HEADS];
    __shared__ float s_inv[RPB][HEADS];
    __shared__ int   s_cnt[RPB];

    const int blk  = blockIdx.x;
    const int row0 = blk * RPB;
    const int b    = row0 >> 10;
    const int t    = threadIdx.x;

    if (t < RPB) s_cnt[t] = 0;
    if (t < RPB * HEADS) s_self[t >> 3][t & 7] = self_t[(row0 + (t >> 3)) * HEADS + (t & 7)];
    __syncthreads();

    {
        const int r   = t >> 6;
        const int c64 = t & 63;
        const float4* Arow = (const float4*)(A + (long)(row0 + r) * NNODES);
        const float4 v0 = Arow[c64];
        const float4 v1 = Arow[c64 + 64];
        const float4 v2 = Arow[c64 + 128];
        const float4 v3 = Arow[c64 + 192];
        int idx[8]; int c = 0;
        const int b0 = c64 * 4;
        if (v0.x != 0.0f) idx[c++] = b0 + 0;
        if (v0.y != 0.0f) idx[c++] = b0 + 1;
        if (v0.z != 0.0f) idx[c++] = b0 + 2;
        if (v0.w != 0.0f) idx[c++] = b0 + 3;
        if (v1.x != 0.0f) idx[c++] = b0 + 256;
        if (v1.y != 0.0f) idx[c++] = b0 + 257;
        if (v1.z != 0.0f) idx[c++] = b0 + 258;
        if (v1.w != 0.0f) idx[c++] = b0 + 259;
        int idx2[8]; int c2 = 0;
        if (v2.x != 0.0f) idx2[c2++] = b0 + 512;
        if (v2.y != 0.0f) idx2[c2++] = b0 + 513;
        if (v2.z != 0.0f) idx2[c2++] = b0 + 514;
        if (v2.w != 0.0f) idx2[c2++] = b0 + 515;
        if (v3.x != 0.0f) idx2[c2++] = b0 + 768;
        if (v3.y != 0.0f) idx2[c2++] = b0 + 769;
        if (v3.z != 0.0f) idx2[c2++] = b0 + 770;
        if (v3.w != 0.0f) idx2[c2++] = b0 + 771;
        if (c + c2) {
            int p = atomicAdd(&s_cnt[r], c + c2);
            for (int i = 0; i < c; i++)  nbr[r][p + i] = idx[i];
            for (int i = 0; i < c2; i++) nbr[r][p + c + i] = idx2[i];
        }
    }
    __syncthreads();

    {
        const int w = t >> 5, lane = t & 31;
        const float* nb = neigh_t + (long)b * NNODES * HEADS;
#pragma unroll
        for (int p = 0; p < 4; p++) {
            const int pair = w * 4 + p;
            const int pr = pair >> 3, ph = pair & 7;
            const int M = s_cnt[pr];
            const float sw = s_self[pr][ph];
            float mx = -1e30f;
            for (int j = lane; j < M; j += 32) {
                float s = sw + nb[nbr[pr][j] * HEADS + ph];
                s = (s > 0.0f) ? s : 0.01f * s;
                sc[pr][ph][j] = s;
                mx = fmaxf(mx, s);
            }
#pragma unroll
            for (int o = 16; o > 0; o >>= 1) mx = fmaxf(mx, __shfl_xor_sync(0xffffffffu, mx, o));
            float sum = 0.0f;
            for (int j = lane; j < M; j += 32) {
                float e = __expf(sc[pr][ph][j] - mx);
                sc[pr][ph][j] = e;
                sum += e;
            }
#pragma unroll
            for (int o = 16; o > 0; o >>= 1) sum += __shfl_xor_sync(0xffffffffu, sum, o);
            if (lane == 0) s_inv[pr][ph] = 1.0f / sum;
        }
    }
    __syncthreads();

    {
        const int w = t >> 5, lane = t & 31;
        const int r  = w >> 1;
        const int cq = (w & 1) * 32 + lane;
        const int h  = cq >> 3;
        const int M  = s_cnt[r];
        const float* scr = sc[r][h];
        const int* nbrr = nbr[r];
        const float4* inpb = (const float4*)inp + (long)b * NNODES * (OUT_DIM / 4);

        float4 a0 = make_float4(0.f, 0.f, 0.f, 0.f);
        float4 a1 = make_float4(0.f, 0.f, 0.f, 0.f);
        float4 a2 = make_float4(0.f, 0.f, 0.f, 0.f);
        float4 a3 = make_float4(0.f, 0.f, 0.f, 0.f);
        int j = 0;
        for (; j + 3 < M; j += 4) {
            const int i0 = nbrr[j],     i1 = nbrr[j + 1];
            const int i2 = nbrr[j + 2], i3 = nbrr[j + 3];
            const float w0 = scr[j],     w1 = scr[j + 1];
            const float w2 = scr[j + 2], w3 = scr[j + 3];
            const float4 v0 = inpb[i0 * 64 + cq];
            const float4 v1 = inpb[i1 * 64 + cq];
            const float4 v2 = inpb[i2 * 64 + cq];
            const float4 v3 = inpb[i3 * 64 + cq];
            a0.x += w0 * v0.x; a0.y += w0 * v0.y; a0.z += w0 * v0.z; a0.w += w0 * v0.w;
            a1.x += w1 * v1.x; a1.y += w1 * v1.y; a1.z += w1 * v1.z; a1.w += w1 * v1.w;
            a2.x += w2 * v2.x; a2.y += w2 * v2.y; a2.z += w2 * v2.z; a2.w += w2 * v2.w;
            a3.x += w3 * v3.x; a3.y += w3 * v3.y; a3.z += w3 * v3.z; a3.w += w3 * v3.w;
        }
        for (; j < M; j++) {
            const int i0 = nbrr[j];
            const float w0 = scr[j];
            const float4 v0 = inpb[i0 * 64 + cq];
            a0.x += w0 * v0.x; a0.y += w0 * v0.y; a0.z += w0 * v0.z; a0.w += w0 * v0.w;
        }
        const float inv = s_inv[r][h];
        float4 o;
        o.x = fmaxf(((a0.x + a1.x) + (a2.x + a3.x)) * inv, 0.0f);
        o.y = fmaxf(((a0.y + a1.y) + (a2.y + a3.y)) * inv, 0.0f);
        o.z = fmaxf(((a0.z + a1.z) + (a2.z + a3.z)) * inv, 0.0f);
        o.w = fmaxf(((a0.w + a1.w) + (a2.w + a3.w)) * inv, 0.0f);
        *(float4*)&out[(long)(row0 + r) * OUT_DIM + cq * 4] = o;
    }
}

// ---------------- launch ----------------
extern "C" void kernel_launch(void* const* d_in, const int* in_sizes, int n_in,
                              void* d_out, int out_size) {
    const float* A   = (const float*)d_in[0];
    const float* X   = (const float*)d_in[1];
    const float* W   = (const float*)d_in[2];
    const float* fc1 = (const float*)d_in[3];
    const float* fc2 = (const float*)d_in[4];
    float* out = (float*)d_out;

    float *inp, *self_t, *neigh_t;
    cudaGetSymbolAddress((void**)&inp,     g_inputs);
    cudaGetSymbolAddress((void**)&self_t,  g_self);
    cudaGetSymbolAddress((void**)&neigh_t, g_neigh);

    dim3 ggrid(OUT_DIM / BN, ROWS / BM);   // (4, 64)
    gemm_tf32_kernel<<<ggrid, 256>>>(X, W, inp);
    scores_kernel<<<ROWS, 256>>>(inp, fc1, fc2, self_t, neigh_t);
    attn_kernel<<<ROWS / RPB, 256>>>(A, inp, self_t, neigh_t, out);
}